// round 15
// baseline (speedup 1.0000x reference)
#include <cuda_runtime.h>
#include <cstdint>

// Shapes: x[8,64,512,512] f32, W[64,64], b[64], seg_w[4,4] -> out[8,64,512,512]
// SEG=4 -> 128x128 blocks. A "band" = one (b,c,i) slab of 128 rows = 16384 float4.
// 2048 bands. Measured: standalone pool 77.9us @30regs, bcast 78-79us,
// ~16us fixed harness overhead. Fused-pool regression chain:
//   R12 gated exits (sync) -> R13 __threadfence (L1 flush) -> R14 reg inflation.
// R15 = fence-free + non-gating + reg-capped (256,8).
#define Bb 8
#define Cc 64
#define Oo 64
#define BAND_F4 16384
#define NBAND   2048

// scratch (__device__ globals: allocation-free rule)
__device__ __align__(16) float g_pooled[Bb*Cc*16];   // [b][c][i*4+j], mean-scaled
__device__ float g_weighted[Bb*Oo*16];               // [b][o][i*4+j]
__device__ int   g_cnt[Bb];                          // per-batch arrival counters

__device__ __forceinline__ void red_release_add(int* addr, int val) {
    asm volatile("red.release.gpu.global.add.s32 [%0], %1;"
                 :: "l"(addr), "r"(val) : "memory");
}
__device__ __forceinline__ int ld_acquire(const int* addr) {
    int v;
    asm volatile("ld.acquire.gpu.global.s32 %0, [%1];"
                 : "=r"(v) : "l"(addr) : "memory");
    return v;
}

// ---------------------------------------------------------------------------
// Kernel 1: pool (+ 8 waiter CTAs computing the tiny linear).
// Reg-capped to 32 (8 CTAs/SM) so the streaming path keeps R1's occupancy.
// blockIdx < 2048 : R1's exact streaming body; tid0 appends one float4 store
//                   + one red.release. No fence, no exit gating.
// blockIdx >= 2048: waiter for batch b; acquire-polls, then 64x16 linear.
// ---------------------------------------------------------------------------
__global__ void __launch_bounds__(256, 8) pool_kernel(
    const float4* __restrict__ x,
    const float*  __restrict__ Wm,
    const float*  __restrict__ bias,
    const float*  __restrict__ segw)
{
    const int tid = threadIdx.x;

    if (blockIdx.x >= NBAND) {
        // ---- waiter CTA: linear for batch b once its 256 pools arrived
        const int b = blockIdx.x - NBAND;
        if (tid == 0) {
            while (ld_acquire(&g_cnt[b]) != 256) __nanosleep(256);
        }
        __syncthreads();

        for (int k = 0; k < 4; k++) {
            const int idx2 = tid + k * 256;          // 0..1023
            const int o = idx2 >> 4, ij = idx2 & 15;
            const float* p  = g_pooled + (b * Cc) * 16 + ij;
            const float* wr = Wm + o * Cc;
            float a = bias[o];
            #pragma unroll 4
            for (int c = 0; c < Cc; c++)
                a = fmaf(__ldcg(&p[c * 16]), wr[c], a);
            g_weighted[(b * Oo + o) * 16 + ij] = a * segw[ij];
        }
        return;
    }

    // ---- pool CTA: R1's exact streaming body
    const int g = blockIdx.x;                        // band index 0..2047
    const float4* base = x + (size_t)g * BAND_F4;

    float acc = 0.0f;
    #pragma unroll 8
    for (int idx = tid; idx < BAND_F4; idx += 256) {
        float4 v = base[idx];
        acc += (v.x + v.y) + (v.z + v.w);
    }

    #pragma unroll
    for (int off = 16; off; off >>= 1)
        acc += __shfl_xor_sync(0xffffffffu, acc, off);

    __shared__ float ws[8];
    const int warp = tid >> 5;
    if ((tid & 31) == 0) ws[warp] = acc;             // warp w covers j = w&3
    __syncthreads();

    if (tid == 0) {
        const float inv = 1.0f / 16384.0f;
        float4 r = make_float4((ws[0] + ws[4]) * inv,
                               (ws[1] + ws[5]) * inv,
                               (ws[2] + ws[6]) * inv,
                               (ws[3] + ws[7]) * inv);
        *reinterpret_cast<float4*>(&g_pooled[(g >> 2) * 16 + (g & 3) * 4]) = r;
        red_release_add(&g_cnt[g >> 8], 1);          // release-orders the store
    }
    // everyone else exits immediately
}

// ---------------------------------------------------------------------------
// Kernel 2: broadcast (R1 body, evict-first stores; measured 79.0us).
// One CTA per band (b,o,i); column segment j loop-invariant; pure streaming.
// Also resets g_cnt for the next graph replay (pool is quiescent now).
// ---------------------------------------------------------------------------
__global__ __launch_bounds__(256) void bcast_kernel(float4* __restrict__ out)
{
    if (blockIdx.x == 0 && threadIdx.x < Bb) g_cnt[threadIdx.x] = 0;

    const int g  = blockIdx.x;                       // band index 0..2047
    const int bo = g >> 2;                           // b*O + o
    const int i  = g & 3;

    const float* wv = g_weighted + bo * 16 + i * 4;
    const int j = (threadIdx.x & 127) >> 5;          // fixed per thread
    const float v = wv[j];
    const float4 f = make_float4(v, v, v, v);

    float4* base = out + (size_t)bo * (4 * BAND_F4) + (size_t)i * BAND_F4;

    #pragma unroll 8
    for (int idx = threadIdx.x; idx < BAND_F4; idx += 256)
        __stcs(&base[idx], f);
}

// ---------------------------------------------------------------------------
extern "C" void kernel_launch(void* const* d_in, const int* in_sizes, int n_in,
                              void* d_out, int out_size)
{
    const float4* x    = (const float4*)d_in[0];
    const float*  Wm   = (const float*)d_in[1];
    const float*  bias = (const float*)d_in[2];
    const float*  segw = (const float*)d_in[3];
    float4* out = (float4*)d_out;

    pool_kernel<<<NBAND + Bb, 256>>>(x, Wm, bias, segw);
    bcast_kernel<<<NBAND, 256>>>(out);
}

// round 16
// speedup vs baseline: 1.0545x; 1.0545x over previous
#include <cuda_runtime.h>
#include <cstdint>

// Shapes: x[8,64,512,512] f32, W[64,64], b[64], seg_w[4,4] -> out[8,64,512,512]
// SEG=4 -> 128x128 blocks. A "band" = one (b,c,i) slab of 128 rows = 16384 float4.
// Proven-best components (measured): pool 77.9us (static 2048 CTAs, 30 regs),
// linear ~1.5us, bcast 78.0us (static 2048, plain stores). All fusion attempts
// regressed the pool stream; this build = R1 structure + PDL to hide the
// inter-kernel launch gaps (dependent CTAs staged on-SM, memory ordering via
// cudaGridDependencySynchronize).
#define Bb 8
#define Cc 64
#define Oo 64
#define BAND_F4 16384
#define NBAND   2048

// scratch (__device__ globals: allocation-free rule)
__device__ float g_pooled[Bb*Cc*16];     // [b][c][i*4+j], mean-scaled
__device__ float g_weighted[Bb*Oo*16];   // [b][o][i*4+j]

// ---------------------------------------------------------------------------
// Kernel 1: segment mean pool (R1 exact body). One CTA per band (b,c,i).
// Trigger fires after the streaming loop: dependents may stage while the
// reduce/store tail (~100 cycles) and remaining CTAs finish.
// ---------------------------------------------------------------------------
__global__ __launch_bounds__(256) void pool_kernel(const float4* __restrict__ x)
{
    const int g = blockIdx.x;                    // band index 0..2047
    const float4* base = x + (size_t)g * BAND_F4;

    float acc = 0.0f;
    #pragma unroll 8
    for (int idx = threadIdx.x; idx < BAND_F4; idx += 256) {
        float4 v = base[idx];
        acc += (v.x + v.y) + (v.z + v.w);
    }

    cudaTriggerProgrammaticLaunchCompletion();   // launch-gate only, not memory

    #pragma unroll
    for (int off = 16; off; off >>= 1)
        acc += __shfl_xor_sync(0xffffffffu, acc, off);

    __shared__ float ws[8];
    const int warp = threadIdx.x >> 5;
    if ((threadIdx.x & 31) == 0) ws[warp] = acc; // warp w covers j = w&3
    __syncthreads();

    if (threadIdx.x < 4) {
        const float inv = 1.0f / 16384.0f;
        g_pooled[(g >> 2) * 16 + (g & 3) * 4 + threadIdx.x] =
            (ws[threadIdx.x] + ws[threadIdx.x + 4]) * inv;
    }
}

// ---------------------------------------------------------------------------
// Kernel 2: tiny linear + bias + seg scale (R1 exact body). 8192 outputs.
// Grid-dep sync makes all pool writes visible; triggers bcast staging at once.
// ---------------------------------------------------------------------------
__global__ __launch_bounds__(256) void linear_kernel(
    const float* __restrict__ Wm,
    const float* __restrict__ bias,
    const float* __restrict__ seg_w)
{
    cudaGridDependencySynchronize();             // wait: pool grid complete
    cudaTriggerProgrammaticLaunchCompletion();   // let bcast stage now

    const int idx = blockIdx.x * 256 + threadIdx.x;   // 0 .. 8191
    if (idx >= Bb * Oo * 16) return;

    const int ij = idx & 15;
    const int o  = (idx >> 4) & (Oo - 1);
    const int b  = idx >> 10;

    const float* p    = g_pooled + b * (Cc * 16) + ij;
    const float* wrow = Wm + o * Cc;

    float acc = bias[o];
    #pragma unroll
    for (int c = 0; c < Cc; c++)
        acc = fmaf(p[c * 16], wrow[c], acc);

    g_weighted[idx] = acc * seg_w[ij];
}

// ---------------------------------------------------------------------------
// Kernel 3: broadcast (R1 exact body, plain stores -- 78.0us measured).
// One CTA per band (b,o,i); column segment j loop-invariant; pure streaming.
// ---------------------------------------------------------------------------
__global__ __launch_bounds__(256) void bcast_kernel(float4* __restrict__ out)
{
    cudaGridDependencySynchronize();             // wait: linear grid complete

    const int g  = blockIdx.x;                   // band index 0..2047
    const int bo = g >> 2;                       // b*O + o
    const int i  = g & 3;

    const float* wv = g_weighted + bo * 16 + i * 4;
    const int j = (threadIdx.x & 127) >> 5;      // fixed per thread
    const float v = wv[j];
    const float4 f = make_float4(v, v, v, v);

    float4* base = out + (size_t)bo * (4 * BAND_F4) + (size_t)i * BAND_F4;

    #pragma unroll 8
    for (int idx = threadIdx.x; idx < BAND_F4; idx += 256)
        base[idx] = f;
}

// ---------------------------------------------------------------------------
// Host: PDL-chained launches (fallback to plain launches if Ex fails).
// ---------------------------------------------------------------------------
template <typename K, typename... Args>
static inline void launch_pdl(K kernel, dim3 grid, bool pdl, Args... args)
{
    cudaLaunchConfig_t cfg = {};
    cfg.gridDim  = grid;
    cfg.blockDim = dim3(256, 1, 1);
    cfg.dynamicSmemBytes = 0;
    cfg.stream = 0;
    cudaLaunchAttribute attr[1];
    if (pdl) {
        attr[0].id = cudaLaunchAttributeProgrammaticStreamSerialization;
        attr[0].val.programmaticStreamSerializationAllowed = 1;
        cfg.attrs = attr;
        cfg.numAttrs = 1;
    }
    cudaError_t e = cudaLaunchKernelEx(&cfg, kernel, args...);
    if (e != cudaSuccess) {                      // fallback: plain launch
        cudaGetLastError();
        kernel<<<grid, 256>>>(args...);
    }
}

extern "C" void kernel_launch(void* const* d_in, const int* in_sizes, int n_in,
                              void* d_out, int out_size)
{
    const float4* x    = (const float4*)d_in[0];
    const float*  Wm   = (const float*)d_in[1];
    const float*  bias = (const float*)d_in[2];
    const float*  segw = (const float*)d_in[3];
    float4* out = (float4*)d_out;

    launch_pdl(pool_kernel,   dim3(NBAND), false, x);
    launch_pdl(linear_kernel, dim3((Bb*Oo*16 + 255) / 256), true, Wm, bias, segw);
    launch_pdl(bcast_kernel,  dim3(NBAND), true, out);
}